// round 4
// baseline (speedup 1.0000x reference)
#include <cuda_runtime.h>

#define NSEG   128
#define SDIM   32
#define TDIM   32
#define NWARPS 4
#define NTHREADS 128
#define SPLIT  6
#define NBINS  34                 // bin = r+1, r in [-1, 32]
#define PITCH  33                 // float2 granules per bin: bankpair=(bin+t)%16

__device__ int g_bounds[NSEG + 1];

__device__ __forceinline__ long long ld_idx(const void* p, int i, bool is64) {
    return is64 ? ((const long long*)p)[i] : (long long)((const int*)p)[i];
}

// kernel 1: zero output + all 129 segment lower_bounds (one warp each)
__global__ void __launch_bounds__(256)
prep_kernel(const void* __restrict__ idxraw, float* __restrict__ out,
            int out_n, int N)
{
    const int gtid = blockIdx.x * blockDim.x + threadIdx.x;
    for (int i = gtid; i < out_n; i += gridDim.x * blockDim.x) out[i] = 0.f;

    const int gw = gtid >> 5;
    const int t  = gtid & 31;
    if (gw > NSEG) return;

    const bool is64 = (((const int*)idxraw)[(N - 2) | 1] == 0);
    const long long T = (long long)gw;
    int lo = 0, hi = N;
    long long first = ld_idx(idxraw, 0, is64);
    if (first >= T) {
        hi = 0;
    } else {
        // invariant: idx[lo] < T, answer in (lo, hi]
        while (hi - lo > 1) {
            long long span = (long long)(hi - lo);
            int pos = lo + (int)((span * (long long)t) >> 5);
            long long val = ld_idx(idxraw, pos, is64);
            unsigned m = __ballot_sync(0xFFFFFFFFu, val < T);
            int k = __popc(m);                 // >= 1 (lane 0 probes lo)
            int nl = lo + (int)((span * (long long)(k - 1)) >> 5);
            int nh = (k < 32) ? lo + (int)((span * (long long)k) >> 5) : hi;
            lo = nl; hi = nh;
        }
    }
    if (t == 0) g_bounds[gw] = hi;
}

__global__ void __launch_bounds__(NTHREADS, 6)
ect_kernel(const float* __restrict__ x, const float* __restrict__ v,
           const float* __restrict__ lin, const void* __restrict__ scaleraw,
           float* __restrict__ out)
{
    // per-warp interleaved accumulators: {count, sigsum} per (bin, t)
    __shared__ float2 acc[NWARPS][NBINS * PITCH];

    const int tid = threadIdx.x;
    const int w   = tid >> 5;
    const int t   = tid & 31;
    const int seg  = (int)blockIdx.x / SPLIT;
    const int part = (int)blockIdx.x - seg * SPLIT;

    // zero accumulators
    float2* accF = &acc[0][0];
    for (int i = tid; i < NWARPS * NBINS * PITCH; i += NTHREADS)
        accF[i] = make_float2(0.f, 0.f);

    const int segS = __ldg(&g_bounds[seg]);
    const int segE = __ldg(&g_bounds[seg + 1]);

    // scale: int32/int64 low word, or float32
    int s_i = *(const int*)scaleraw;
    const float scale = (s_i > 0 && s_i < 1000000) ? (float)s_i
                                                   : *(const float*)scaleraw;

    const float lin0   = lin[0];
    const float dl     = (lin[SDIM - 1] - lin0) * (1.0f / (SDIM - 1));
    const float inv_dl = 1.0f / dl;
    const float KSdl   = scale * 1.4426950408889634f * dl;  // ~35.5 (log2 units)
    const float nb     = -lin0 * inv_dl;

    const float v0 = v[t], v1 = v[TDIM + t], v2 = v[2 * TDIM + t];

    const int chunk = (segE - segS + SPLIT - 1) / SPLIT;
    int start = segS + part * chunk;
    if (start > segE) start = segE;
    int end = start + chunk;
    if (end > segE) end = segE;

    int gs = (start + 3) & ~3;                    // first float4-aligned node
    if (gs > end) gs = end;
    const int ge = gs + ((end - gs) & ~3);

    float2* aW = &acc[w][0] + t;                  // lane-offset base

    // out[s] = #{r_n < s} + sum_{r_n = s} sg_n ; stored at bin = r+1:
    //   acc[bin] += {1, sg}.  Clamp keeps bin in [0,33]; slots outside the
    //   read window (C: bin<=31, E: 1<=bin<=32) are provably negligible.
    auto proc = [&](float nh) {
        float u = fmaf(nh, inv_dl, nb);
        u = fminf(fmaxf(u, -0.6f), 32.4f);
        float r = rintf(u);
        float z = KSdl * (u - r);                  // |z| <= 17.75
        int bin = (int)r + 1;                      // [0, 33]
        float g;  asm("ex2.approx.f32 %0, %1;" : "=f"(g)  : "f"(z));
        float sg; asm("rcp.approx.f32 %0, %1;" : "=f"(sg) : "f"(1.f + g));
        float2 cur = aW[bin * PITCH];              // single LDS.64
        cur.x += 1.0f;
        cur.y += sg;
        aW[bin * PITCH] = cur;                     // single STS.64
    };

    // main loop: 4 nodes/iter, 3x float4 broadcast loads
    for (int n = gs + w * 4; n < ge; n += NWARPS * 4) {
        const float4* xp = (const float4*)(x + 3 * n);
        float4 A = __ldg(xp), B = __ldg(xp + 1), C = __ldg(xp + 2);
        float nh0 = fmaf(A.z, v2, fmaf(A.y, v1, A.x * v0));
        float nh1 = fmaf(B.y, v2, fmaf(B.x, v1, A.w * v0));
        float nh2 = fmaf(C.x, v2, fmaf(B.w, v1, B.z * v0));
        float nh3 = fmaf(C.w, v2, fmaf(C.z, v1, C.y * v0));
        proc(nh0); proc(nh1); proc(nh2); proc(nh3);
    }
    // scalar remainders (<= 3 each side), warp 0
    if (w == 0) {
        for (int n = start; n < gs; n++) {
            const float* xp = x + 3 * n;
            proc(fmaf(__ldg(xp + 2), v2, fmaf(__ldg(xp + 1), v1, __ldg(xp) * v0)));
        }
        for (int n = ge; n < end; n++) {
            const float* xp = x + 3 * n;
            proc(fmaf(__ldg(xp + 2), v2, fmaf(__ldg(xp + 1), v1, __ldg(xp) * v0)));
        }
    }
    __syncthreads();

    // reduce the 4 private copies into copy 0 (only live (bin,t) slots)
    for (int i = tid; i < NBINS * 32; i += NTHREADS) {
        int b = i >> 5, tt = i & 31, o = b * PITCH + tt;
        float2 s0 = acc[0][o], s1 = acc[1][o], s2 = acc[2][o], s3 = acc[3][o];
        float2 rr;
        rr.x = (s0.x + s1.x) + (s2.x + s3.x);
        rr.y = (s0.y + s1.y) + (s2.y + s3.y);
        acc[0][o] = rr;
    }
    __syncthreads();

    // out[s] = prefixIncl(C)[s] + E[s+1]; warp 0, lane t owns column t
    if (w == 0) {
        float run = 0.f;
        float* ob = out + seg * (SDIM * TDIM) + t;
        #pragma unroll
        for (int b = 0; b <= SDIM; b++) {
            float2 cv = acc[0][b * PITCH + t];     // {C[b], E[b]}
            if (b >= 1) atomicAdd(ob + (b - 1) * TDIM, run + cv.y);
            run += cv.x;
        }
    }
}

extern "C" void kernel_launch(void* const* d_in, const int* in_sizes, int n_in,
                              void* d_out, int out_size)
{
    const float* x     = (const float*)d_in[0];
    const void*  index = d_in[1];
    const float* v     = (const float*)d_in[2];
    const float* lin   = (const float*)d_in[3];
    const void*  scale = d_in[4];
    float*       out   = (float*)d_out;
    const int N = in_sizes[1];

    prep_kernel<<<17, 256>>>(index, out, out_size, N);
    ect_kernel<<<NSEG * SPLIT, NTHREADS>>>(x, v, lin, scale, out);
}

// round 5
// speedup vs baseline: 1.2145x; 1.2145x over previous
#include <cuda_runtime.h>
#include <cuda_fp16.h>

#define NSEG   128
#define SDIM   32
#define TDIM   32
#define NWARPS 4
#define NTHREADS 128
#define SPLIT  12
#define NBINS  34                 // bin = r+1, r in [-1, 32]
#define PITCH  33                 // 4B-bank index (33*bin+t)%32 == (bin+t)%32

__device__ int g_bounds[NSEG + 1];

__device__ __forceinline__ long long ld_idx(const void* p, int i, bool is64) {
    return is64 ? ((const long long*)p)[i] : (long long)((const int*)p)[i];
}

// prep: zero output + segment boundaries via flat parallel scan (no dependent loads)
__global__ void __launch_bounds__(256)
prep_kernel(const void* __restrict__ idxraw, float* __restrict__ out,
            int out_n, int N)
{
    const int gtid   = blockIdx.x * blockDim.x + threadIdx.x;
    const int stride = gridDim.x * blockDim.x;

    for (int i = gtid; i < out_n; i += stride) out[i] = 0.f;

    const bool is64 = (((const int*)idxraw)[(N - 2) | 1] == 0);
    for (int i = gtid; i < N; i += stride) {
        int a = (int)ld_idx(idxraw, i, is64);
        int b = (i + 1 < N) ? (int)ld_idx(idxraw, i + 1, is64) : NSEG;
        if (i == 0)
            for (int j = 0; j <= a; j++) g_bounds[j] = 0;
        for (int j = a + 1; j <= b; j++) g_bounds[j] = i + 1;
    }
}

__global__ void __launch_bounds__(NTHREADS, 10)
ect_kernel(const float* __restrict__ x, const float* __restrict__ v,
           const float* __restrict__ lin, const void* __restrict__ scaleraw,
           float* __restrict__ out)
{
    // per-warp accumulators: half2 {count, sig} per (bin, t)  (4.5 KB/warp)
    __shared__ __half2 acc[NWARPS][NBINS * PITCH];

    const int tid = threadIdx.x;
    const int w   = tid >> 5;
    const int t   = tid & 31;
    const int seg  = (int)blockIdx.x / SPLIT;
    const int part = (int)blockIdx.x - seg * SPLIT;

    // zero accumulators
    unsigned* accU = (unsigned*)&acc[0][0];
    #pragma unroll
    for (int i = tid; i < NWARPS * NBINS * PITCH; i += NTHREADS)
        accU[i] = 0u;

    const int segS = g_bounds[seg];
    const int segE = g_bounds[seg + 1];

    // scale: int32/int64 low word, or float32
    int s_i = *(const int*)scaleraw;
    const float scale = (s_i > 0 && s_i < 1000000) ? (float)s_i
                                                   : *(const float*)scaleraw;

    const float lin0   = lin[0];
    const float dl     = (lin[SDIM - 1] - lin0) * (1.0f / (SDIM - 1));
    const float inv_dl = 1.0f / dl;
    const float KSdl   = scale * 1.4426950408889634f * dl;  // ~35.5 (log2 units)
    const float nb     = -lin0 * inv_dl;
    const float MAGIC  = 12582912.0f;                        // 2^23 + 2^22
    const int   MAGICI = 0x4B400000;

    const float v0 = v[t], v1 = v[TDIM + t], v2 = v[2 * TDIM + t];

    const int chunk = (segE - segS + SPLIT - 1) / SPLIT;
    int start = segS + part * chunk;
    if (start > segE) start = segE;
    int end = start + chunk;
    if (end > segE) end = segE;

    int gs = (start + 3) & ~3;                    // first float4-aligned node
    if (gs > end) gs = end;
    const int ge = gs + ((end - gs) & ~3);

    __half2* aW = &acc[w][0] + t;                  // lane-offset base

    // out[s] = #{r_n < s} + sum_{r_n = s} sg_n, stored at bin = r+1 as {1, sg}.
    auto proc = [&](float nh) {
        float u = fmaf(nh, inv_dl, nb);
        u = fminf(fmaxf(u, -0.6f), 32.4f);
        float f = u + MAGIC;                       // round-to-nearest via magic
        int  ir = __float_as_int(f) - MAGICI;      // = rint(u)
        float r = f - MAGIC;
        float z = KSdl * (u - r);                  // |z| <= 17.75
        float g;  asm("ex2.approx.f32 %0, %1;" : "=f"(g)  : "f"(z));
        float sg; asm("rcp.approx.f32 %0, %1;" : "=f"(sg) : "f"(1.f + g));
        __half2 inc = __floats2half2_rn(1.0f, sg); // {count=1, sig=sg}
        int off = (ir + 1) * PITCH;                // bin in [0, 33]
        aW[off] = __hadd2(aW[off], inc);           // LDS.32 + HADD2 + STS.32
    };

    // main loop: 4 nodes/iter, 3x float4 broadcast loads
    for (int n = gs + w * 4; n < ge; n += NWARPS * 4) {
        const float4* xp = (const float4*)(x + 3 * n);
        float4 A = __ldg(xp), B = __ldg(xp + 1), C = __ldg(xp + 2);
        float nh0 = fmaf(A.z, v2, fmaf(A.y, v1, A.x * v0));
        float nh1 = fmaf(B.y, v2, fmaf(B.x, v1, A.w * v0));
        float nh2 = fmaf(C.x, v2, fmaf(B.w, v1, B.z * v0));
        float nh3 = fmaf(C.w, v2, fmaf(C.z, v1, C.y * v0));
        proc(nh0); proc(nh1); proc(nh2); proc(nh3);
    }
    // scalar remainders (<= 3 each side), warp 0
    if (w == 0) {
        for (int n = start; n < gs; n++) {
            const float* xp = x + 3 * n;
            proc(fmaf(__ldg(xp + 2), v2, fmaf(__ldg(xp + 1), v1, __ldg(xp) * v0)));
        }
        for (int n = ge; n < end; n++) {
            const float* xp = x + 3 * n;
            proc(fmaf(__ldg(xp + 2), v2, fmaf(__ldg(xp + 1), v1, __ldg(xp) * v0)));
        }
    }
    __syncthreads();

    // warp 0: fused reduce(4 copies) + prefix over bins + RED into out
    // out[s] = prefixIncl(C)[s] + E[s+1]
    if (w == 0) {
        float run = 0.f;
        float* ob = out + seg * (SDIM * TDIM) + t;
        #pragma unroll
        for (int b = 0; b <= SDIM; b++) {
            int o = b * PITCH + t;
            __half2 h0 = acc[0][o], h1 = acc[1][o], h2 = acc[2][o], h3 = acc[3][o];
            float2 f0 = __half22float2(h0), f1 = __half22float2(h1);
            float2 f2 = __half22float2(h2), f3 = __half22float2(h3);
            float C = (f0.x + f1.x) + (f2.x + f3.x);
            float E = (f0.y + f1.y) + (f2.y + f3.y);
            if (b >= 1) atomicAdd(ob + (b - 1) * TDIM, run + E);
            run += C;
        }
    }
}

extern "C" void kernel_launch(void* const* d_in, const int* in_sizes, int n_in,
                              void* d_out, int out_size)
{
    const float* x     = (const float*)d_in[0];
    const void*  index = d_in[1];
    const float* v     = (const float*)d_in[2];
    const float* lin   = (const float*)d_in[3];
    const void*  scale = d_in[4];
    float*       out   = (float*)d_out;
    const int N = in_sizes[1];

    prep_kernel<<<256, 256>>>(index, out, out_size, N);
    ect_kernel<<<NSEG * SPLIT, NTHREADS>>>(x, v, lin, scale, out);
}

// round 6
// speedup vs baseline: 1.3617x; 1.1212x over previous
#include <cuda_runtime.h>
#include <cuda_fp16.h>

#define NSEG   128
#define SDIM   32
#define TDIM   32
#define NWARPS 4
#define NTHREADS 128
#define SPLIT  11
#define NBINS  34                 // bin = r+1, r in [-1, 32]
#define PITCH  33                 // 4B-bank index (33*bin+t)%32 == (bin+t)%32

__device__ int g_bounds[NSEG + 1];

__device__ __forceinline__ long long ld_idx(const void* p, int i, bool is64) {
    return is64 ? ((const long long*)p)[i] : (long long)((const int*)p)[i];
}

// prep: zero output + segment boundaries via flat parallel scan (no dependent loads)
__global__ void __launch_bounds__(256)
prep_kernel(const void* __restrict__ idxraw, float* __restrict__ out,
            int out_n, int N)
{
    const int gtid   = blockIdx.x * blockDim.x + threadIdx.x;
    const int stride = gridDim.x * blockDim.x;

    for (int i = gtid; i < out_n; i += stride) out[i] = 0.f;

    const bool is64 = (((const int*)idxraw)[(N - 2) | 1] == 0);
    for (int i = gtid; i < N; i += stride) {
        int a = (int)ld_idx(idxraw, i, is64);
        int b = (i + 1 < N) ? (int)ld_idx(idxraw, i + 1, is64) : NSEG;
        if (i == 0)
            for (int j = 0; j <= a; j++) g_bounds[j] = 0;
        for (int j = a + 1; j <= b; j++) g_bounds[j] = i + 1;
    }
}

__global__ void __launch_bounds__(NTHREADS, SPLIT)
ect_kernel(const float* __restrict__ x, const float* __restrict__ v,
           const float* __restrict__ lin, const void* __restrict__ scaleraw,
           float* __restrict__ out)
{
    // per-warp accumulators: half2 {count, tanh-sum} per (bin, t)  (4.5 KB/warp)
    __shared__ __half2 acc[NWARPS][NBINS * PITCH];

    const int tid = threadIdx.x;
    const int w   = tid >> 5;
    const int t   = tid & 31;
    const int seg  = (int)blockIdx.x / SPLIT;
    const int part = (int)blockIdx.x - seg * SPLIT;

    // zero accumulators, 16B-vectorized (4488 words = 1122 int4)
    {
        int4* z = (int4*)&acc[0][0];
        const int n16 = (NWARPS * NBINS * PITCH) / 4;    // 1122
        for (int i = tid; i < n16; i += NTHREADS)
            z[i] = make_int4(0, 0, 0, 0);
        // tail words (4488 % 4 == 0, none)
    }

    const int segS = g_bounds[seg];
    const int segE = g_bounds[seg + 1];

    // scale: int32/int64 low word, or float32
    int s_i = *(const int*)scaleraw;
    const float scale = (s_i > 0 && s_i < 1000000) ? (float)s_i
                                                   : *(const float*)scaleraw;

    const float lin0   = lin[0];
    const float dl     = (lin[SDIM - 1] - lin0) * (1.0f / (SDIM - 1));
    const float inv_dl = 1.0f / dl;
    const float K2     = -0.5f * scale * dl;      // tanh arg scale (natural units)
    const float nb     = -lin0 * inv_dl;
    const float MAGIC  = 12582912.0f;             // 2^23 + 2^22
    const int   MAGICI = 0x4B400000;

    const float v0 = v[t], v1 = v[TDIM + t], v2 = v[2 * TDIM + t];

    const int chunk = (segE - segS + SPLIT - 1) / SPLIT;
    int start = segS + part * chunk;
    if (start > segE) start = segE;
    int end = start + chunk;
    if (end > segE) end = segE;

    int gs = (start + 3) & ~3;                    // first float4-aligned node
    if (gs > end) gs = end;
    const int ge = gs + ((end - gs) & ~3);

    __half2* aW = &acc[w][0] + t;                  // lane-offset base

    // Node with nearest boundary r: sig(s) ~ 0 (s<r), sg (s=r), 1 (s>r).
    // sg = 0.5 + 0.5*tanh(K2*(u-r)).  Accumulate {1, tanh} at bin=r+1; the
    // 0.5/0.5 affine is applied once per bin in the epilogue.
    auto proc = [&](float nh) {
        float u = fmaf(nh, inv_dl, nb);
        u = fminf(fmaxf(u, -0.6f), 32.4f);
        float f = u + MAGIC;                       // round-to-nearest via magic
        int  ir = __float_as_int(f) - MAGICI;      // = rint(u)
        float r = f - MAGIC;
        float z = K2 * (u - r);
        float th; asm("tanh.approx.f32 %0, %1;" : "=f"(th) : "f"(z));
        __half2 inc = __floats2half2_rn(1.0f, th); // {count, tanh}
        int off = (ir + 1) * PITCH;                // bin in [0, 33]
        aW[off] = __hadd2(aW[off], inc);           // LDS.32 + HADD2 + STS.32
    };

    // main loop: 4 nodes/iter, 3x float4 broadcast loads
    for (int n = gs + w * 4; n < ge; n += NWARPS * 4) {
        const float4* xp = (const float4*)(x + 3 * n);
        float4 A = __ldg(xp), B = __ldg(xp + 1), C = __ldg(xp + 2);
        float nh0 = fmaf(A.z, v2, fmaf(A.y, v1, A.x * v0));
        float nh1 = fmaf(B.y, v2, fmaf(B.x, v1, A.w * v0));
        float nh2 = fmaf(C.x, v2, fmaf(B.w, v1, B.z * v0));
        float nh3 = fmaf(C.w, v2, fmaf(C.z, v1, C.y * v0));
        proc(nh0); proc(nh1); proc(nh2); proc(nh3);
    }
    // scalar remainders (<= 3 each side), warp 0
    if (w == 0) {
        for (int n = start; n < gs; n++) {
            const float* xp = x + 3 * n;
            proc(fmaf(__ldg(xp + 2), v2, fmaf(__ldg(xp + 1), v1, __ldg(xp) * v0)));
        }
        for (int n = ge; n < end; n++) {
            const float* xp = x + 3 * n;
            proc(fmaf(__ldg(xp + 2), v2, fmaf(__ldg(xp + 1), v1, __ldg(xp) * v0)));
        }
    }
    __syncthreads();

    // warp 0: reduce 4 copies + prefix over bins + RED into out
    // out[s] = prefixIncl(C)[s] + 0.5*(C[s+1] + Th[s+1])
    if (w == 0) {
        float run = 0.f;
        float* ob = out + seg * (SDIM * TDIM) + t;
        #pragma unroll
        for (int b = 0; b <= SDIM; b++) {
            int o = b * PITCH + t;
            __half2 h0 = acc[0][o], h1 = acc[1][o], h2 = acc[2][o], h3 = acc[3][o];
            float2 f0 = __half22float2(h0), f1 = __half22float2(h1);
            float2 f2 = __half22float2(h2), f3 = __half22float2(h3);
            float C  = (f0.x + f1.x) + (f2.x + f3.x);
            float Th = (f0.y + f1.y) + (f2.y + f3.y);
            if (b >= 1) atomicAdd(ob + (b - 1) * TDIM, fmaf(0.5f, C + Th, run));
            run += C;
        }
    }
}

extern "C" void kernel_launch(void* const* d_in, const int* in_sizes, int n_in,
                              void* d_out, int out_size)
{
    const float* x     = (const float*)d_in[0];
    const void*  index = d_in[1];
    const float* v     = (const float*)d_in[2];
    const float* lin   = (const float*)d_in[3];
    const void*  scale = d_in[4];
    float*       out   = (float*)d_out;
    const int N = in_sizes[1];

    prep_kernel<<<256, 256>>>(index, out, out_size, N);
    ect_kernel<<<NSEG * SPLIT, NTHREADS>>>(x, v, lin, scale, out);
}